// round 2
// baseline (speedup 1.0000x reference)
#include <cuda_runtime.h>

// RNN2Classifier: B=4M, T=4, D=2, H=2 Elman cell + Linear(2->1).
// One thread per batch element. Memory-bound: 128MB in + 16MB out.

__device__ __forceinline__ float fast_tanh(float x) {
    // tanh(x) = sign(x) * (1 - 2/(exp(2|x|)+1))
    // Overflow-benign: exp(inf)=inf -> 2/inf=0 -> tanh=+-1.
    float a = fabsf(x);
    float e = __expf(2.0f * a);                 // MUFU.EX2 based
    float t = 1.0f - __fdividef(2.0f, e + 1.0f); // MUFU.RCP based
    return copysignf(t, x);
}

__global__ void __launch_bounds__(256) rnn2_kernel(
    const float4* __restrict__ X,     // [B, 2] float4 = [B,4,2] f32
    const float*  __restrict__ wih,   // [2,2]
    const float*  __restrict__ bih,   // [2]
    const float*  __restrict__ whh,   // [2,2]
    const float*  __restrict__ bhh,   // [2]
    const float*  __restrict__ cw,    // [1,2]
    const float*  __restrict__ cb,    // [1]
    float* __restrict__ out,          // [B,1]
    int B)
{
    int b = blockIdx.x * blockDim.x + threadIdx.x;
    if (b >= B) return;

    // Front-batch both 16B loads (MLP=2).
    float4 xa = X[2 * b];
    float4 xb = X[2 * b + 1];

    // Warp-uniform parameter loads (L1-resident).
    float w00 = wih[0], w01 = wih[1], w10 = wih[2], w11 = wih[3];
    float bi0 = bih[0], bi1 = bih[1];
    float u00 = whh[0], u01 = whh[1], u10 = whh[2], u11 = whh[3];
    float bh0 = bhh[0], bh1 = bhh[1];
    float c0 = cw[0], c1 = cw[1], cbias = cb[0];

    float x0[4] = {xa.x, xa.z, xb.x, xb.z};
    float x1[4] = {xa.y, xa.w, xb.y, xb.w};

    // t = 0: h_{-1} = 0, so recurrent term vanishes.
    float h0 = fast_tanh(fmaf(w00, x0[0], fmaf(w01, x1[0], bi0)) + bh0);
    float h1 = fast_tanh(fmaf(w10, x0[0], fmaf(w11, x1[0], bi1)) + bh1);

    #pragma unroll
    for (int t = 1; t < 4; ++t) {
        float ix0 = fmaf(w00, x0[t], fmaf(w01, x1[t], bi0));
        float ix1 = fmaf(w10, x0[t], fmaf(w11, x1[t], bi1));
        float n0 = fast_tanh(fmaf(u00, h0, fmaf(u01, h1, ix0 + bh0)));
        float n1 = fast_tanh(fmaf(u10, h0, fmaf(u11, h1, ix1 + bh1)));
        h0 = n0;
        h1 = n1;
    }

    out[b] = fmaf(c0, h0, fmaf(c1, h1, cbias));
}

extern "C" void kernel_launch(void* const* d_in, const int* in_sizes, int n_in,
                              void* d_out, int out_size)
{
    const float4* X   = (const float4*)d_in[0];
    const float*  wih = (const float*)d_in[1];
    const float*  bih = (const float*)d_in[2];
    const float*  whh = (const float*)d_in[3];
    const float*  bhh = (const float*)d_in[4];
    const float*  cw  = (const float*)d_in[5];
    const float*  cb  = (const float*)d_in[6];
    float* out = (float*)d_out;

    int B = in_sizes[0] / 8;  // X has B*4*2 floats
    int threads = 256;
    int blocks = (B + threads - 1) / threads;
    rnn2_kernel<<<blocks, threads>>>(X, wih, bih, whh, bhh, cw, cb, out, B);
}

// round 3
// speedup vs baseline: 1.0749x; 1.0749x over previous
#include <cuda_runtime.h>

// RNN2Classifier: B=4M, T=4, D=2, H=2 Elman cell + Linear(2->1).
// One thread per batch element. DRAM-bound target: 128MB in + 16MB out.
// tanh via hardware MUFU.TANH (tanh.approx.f32) - 1 MUFU op per activation.

__device__ __forceinline__ float htanh(float x) {
    float y;
    asm("tanh.approx.f32 %0, %1;" : "=f"(y) : "f"(x));
    return y;
}

__global__ void __launch_bounds__(256) rnn2_kernel(
    const float4* __restrict__ X,     // [B,4,2] f32 viewed as [B,2] float4
    const float*  __restrict__ wih,   // [2,2]
    const float*  __restrict__ bih,   // [2]
    const float*  __restrict__ whh,   // [2,2]
    const float*  __restrict__ bhh,   // [2]
    const float*  __restrict__ cw,    // [1,2]
    const float*  __restrict__ cb,    // [1]
    float* __restrict__ out,          // [B,1]
    int B)
{
    int b = blockIdx.x * blockDim.x + threadIdx.x;
    if (b >= B) return;

    // Front-batch both 16B loads (MLP=2, fully coalesced 512B/warp-instr).
    float4 xa = X[2 * b];
    float4 xb = X[2 * b + 1];

    // Warp-uniform parameter loads (L1-resident after first touch).
    float w00 = wih[0], w01 = wih[1], w10 = wih[2], w11 = wih[3];
    float u00 = whh[0], u01 = whh[1], u10 = whh[2], u11 = whh[3];
    // Fold the two biases into one constant per hidden unit.
    float bs0 = bih[0] + bhh[0];
    float bs1 = bih[1] + bhh[1];
    float c0 = cw[0], c1 = cw[1], cbias = cb[0];

    float x0[4] = {xa.x, xa.z, xb.x, xb.z};
    float x1[4] = {xa.y, xa.w, xb.y, xb.w};

    // t = 0: h_{-1} = 0 -> recurrent term vanishes. 2 FMA + 1 TANH per unit.
    float h0 = htanh(fmaf(w00, x0[0], fmaf(w01, x1[0], bs0)));
    float h1 = htanh(fmaf(w10, x0[0], fmaf(w11, x1[0], bs1)));

    // t = 1..3: 4 FMA + 1 TANH per unit per step.
    #pragma unroll
    for (int t = 1; t < 4; ++t) {
        float n0 = htanh(fmaf(u00, h0, fmaf(u01, h1,
                        fmaf(w00, x0[t], fmaf(w01, x1[t], bs0)))));
        float n1 = htanh(fmaf(u10, h0, fmaf(u11, h1,
                        fmaf(w10, x0[t], fmaf(w11, x1[t], bs1)))));
        h0 = n0;
        h1 = n1;
    }

    out[b] = fmaf(c0, h0, fmaf(c1, h1, cbias));
}

extern "C" void kernel_launch(void* const* d_in, const int* in_sizes, int n_in,
                              void* d_out, int out_size)
{
    const float4* X   = (const float4*)d_in[0];
    const float*  wih = (const float*)d_in[1];
    const float*  bih = (const float*)d_in[2];
    const float*  whh = (const float*)d_in[3];
    const float*  bhh = (const float*)d_in[4];
    const float*  cw  = (const float*)d_in[5];
    const float*  cb  = (const float*)d_in[6];
    float* out = (float*)d_out;

    int B = in_sizes[0] / 8;  // X has B*4*2 floats
    int threads = 256;
    int blocks = (B + threads - 1) / threads;
    rnn2_kernel<<<blocks, threads>>>(X, wih, bih, whh, bhh, cw, cb, out, B);
}